// round 1
// baseline (speedup 1.0000x reference)
#include <cuda_runtime.h>
#include <math.h>

#define BB 8
#define NN 2048
#define DD 128
#define KK 64
#define TT 128   // descriptor rows per block

// Accumulators (scratch): P[b][k][d] and s[b][k]
__device__ float g_P[BB * KK * DD];
__device__ float g_s[BB * KK];

// ---------------------------------------------------------------------------
// Kernel 0: zero accumulators (graph replays require re-zeroing every launch)
// ---------------------------------------------------------------------------
__global__ void nv_zero() {
    int i = blockIdx.x * blockDim.x + threadIdx.x;
    if (i < BB * KK * DD) g_P[i] = 0.f;
    if (i < BB * KK)      g_s[i] = 0.f;
}

// ---------------------------------------------------------------------------
// Kernel 1: per 128-row tile — normalize, GEMM1 (Xn*C^T), softmax,
//           GEMM2 (A^T*Xn), atomic accumulate
// smem layout (floats):
//   Ct  [128][68]  : centroids transposed (d-major), padded
//   xs  [128][128] : normalized descriptors
//   As  [128][64]  : softmax assignments
//   cn2 [64]       : ||c_k||^2
// ---------------------------------------------------------------------------
__global__ __launch_bounds__(256, 1)
void nv_main(const float* __restrict__ x, const float* __restrict__ cent) {
    extern __shared__ float sm[];
    float* Ct  = sm;                      // 128*68 = 8704
    float* xs  = sm + 128 * 68;           // 16384
    float* As  = xs + 128 * 128;          // 8192
    float* cn2 = As + 128 * 64;           // 64

    const int tid = threadIdx.x;
    const int b   = blockIdx.y;
    const int n0  = blockIdx.x * TT;

    if (tid < KK) cn2[tid] = 0.f;
    __syncthreads();

    // ---- load centroids (transposed) + accumulate cn2 ----
    {
        const float4* c4 = (const float4*)cent;
        #pragma unroll
        for (int i = tid; i < KK * DD / 4; i += 256) {
            float4 v = c4[i];
            int k  = i >> 5;        // row (centroid index)
            int d  = (i & 31) * 4;  // dim
            Ct[(d + 0) * 68 + k] = v.x;
            Ct[(d + 1) * 68 + k] = v.y;
            Ct[(d + 2) * 68 + k] = v.z;
            Ct[(d + 3) * 68 + k] = v.w;
            atomicAdd(&cn2[k], v.x * v.x + v.y * v.y + v.z * v.z + v.w * v.w);
        }
    }

    // ---- load x tile + per-row L2 normalize (warp w handles rows 16w..16w+15) ----
    {
        const int w = tid >> 5, l = tid & 31;
        const float4* x4 = (const float4*)(x + ((size_t)b * NN + n0) * DD);
        float4* xs4w = (float4*)xs;
        for (int r = w * 16; r < w * 16 + 16; r++) {
            float4 v = x4[r * 32 + l];
            float ss = v.x * v.x + v.y * v.y + v.z * v.z + v.w * v.w;
            #pragma unroll
            for (int o = 16; o > 0; o >>= 1)
                ss += __shfl_xor_sync(0xffffffffu, ss, o);
            float rinv = 1.0f / fmaxf(sqrtf(ss), 1e-12f);
            float4 o4 = make_float4(v.x * rinv, v.y * rinv, v.z * rinv, v.w * rinv);
            xs4w[r * 32 + l] = o4;
        }
    }
    __syncthreads();

    const float4* xs4 = (const float4*)xs;

    // ---- GEMM1: acc[i][j] = dot(xn[row_i], c[col_j]) ----
    // thread (tm, tn): rows tm*8..+7, cols tn*4..+3
    const int tm = tid >> 4, tn = tid & 15;

    float acc[8][4];
    #pragma unroll
    for (int i = 0; i < 8; i++)
        #pragma unroll
        for (int j = 0; j < 4; j++) acc[i][j] = 0.f;

    for (int kk4 = 0; kk4 < 32; kk4++) {
        float aa[8][4];
        #pragma unroll
        for (int i = 0; i < 8; i++) {
            float4 v = xs4[(tm * 8 + i) * 32 + kk4];
            aa[i][0] = v.x; aa[i][1] = v.y; aa[i][2] = v.z; aa[i][3] = v.w;
        }
        float bb[4][4];
        #pragma unroll
        for (int q = 0; q < 4; q++) {
            float4 v = *(const float4*)&Ct[(kk4 * 4 + q) * 68 + tn * 4];
            bb[q][0] = v.x; bb[q][1] = v.y; bb[q][2] = v.z; bb[q][3] = v.w;
        }
        #pragma unroll
        for (int i = 0; i < 8; i++)
            #pragma unroll
            for (int j = 0; j < 4; j++)
                #pragma unroll
                for (int q = 0; q < 4; q++)
                    acc[i][j] += aa[i][q] * bb[q][j];
    }

    // ---- softmax over k per row: dist = cn2[k] - 2*S (||xn||^2 shift drops) ----
    {
        float cc[4];
        #pragma unroll
        for (int j = 0; j < 4; j++) cc[j] = cn2[tn * 4 + j];

        float4* A4 = (float4*)As;
        #pragma unroll
        for (int i = 0; i < 8; i++) {
            float dj[4];
            float m = -1e30f;
            #pragma unroll
            for (int j = 0; j < 4; j++) {
                dj[j] = cc[j] - 2.f * acc[i][j];
                m = fmaxf(m, dj[j]);
            }
            #pragma unroll
            for (int o = 8; o > 0; o >>= 1)
                m = fmaxf(m, __shfl_xor_sync(0xffffffffu, m, o, 16));
            float s = 0.f;
            #pragma unroll
            for (int j = 0; j < 4; j++) {
                float e = __expf(dj[j] - m);
                dj[j] = e; s += e;
            }
            #pragma unroll
            for (int o = 8; o > 0; o >>= 1)
                s += __shfl_xor_sync(0xffffffffu, s, o, 16);
            float r = 1.f / s;
            A4[(tm * 8 + i) * 16 + tn] =
                make_float4(dj[0] * r, dj[1] * r, dj[2] * r, dj[3] * r);
        }
    }
    __syncthreads();

    // ---- GEMM2: p[j][q] = sum_t A[t][k_j] * xn[t][d_q] ----
    // thread (tk, td): k = tk*4..+3, d = td*8..+7
    const int tk = tm, td = tn;
    float p[4][8];
    #pragma unroll
    for (int j = 0; j < 4; j++)
        #pragma unroll
        for (int q = 0; q < 8; q++) p[j][q] = 0.f;
    float sl[4] = {0.f, 0.f, 0.f, 0.f};

    const float4* A4 = (const float4*)As;
    for (int t = 0; t < TT; t++) {
        float4 av = A4[t * 16 + tk];
        float4 b0 = xs4[t * 32 + td * 2];
        float4 b1 = xs4[t * 32 + td * 2 + 1];
        float av4[4] = {av.x, av.y, av.z, av.w};
        float bbv[8] = {b0.x, b0.y, b0.z, b0.w, b1.x, b1.y, b1.z, b1.w};
        #pragma unroll
        for (int j = 0; j < 4; j++) sl[j] += av4[j];
        #pragma unroll
        for (int j = 0; j < 4; j++)
            #pragma unroll
            for (int q = 0; q < 8; q++)
                p[j][q] += av4[j] * bbv[q];
    }

    // ---- accumulate into global P, s ----
    float* Pb = g_P + b * KK * DD;
    #pragma unroll
    for (int j = 0; j < 4; j++) {
        int k = tk * 4 + j;
        #pragma unroll
        for (int q = 0; q < 8; q++)
            atomicAdd(&Pb[k * DD + td * 8 + q], p[j][q]);
    }
    if (td == 0) {
        #pragma unroll
        for (int j = 0; j < 4; j++)
            atomicAdd(&g_s[b * KK + tk * 4 + j], sl[j]);
    }
}

// ---------------------------------------------------------------------------
// Kernel 2: finalize — vlad = P - s*c, intra-norm per k, global norm, write out
// ---------------------------------------------------------------------------
__global__ __launch_bounds__(512, 1)
void nv_fin(const float* __restrict__ cent, float* __restrict__ out) {
    __shared__ float V[KK * DD];   // 32KB
    __shared__ float ssm[KK];
    __shared__ float gss;

    const int b = blockIdx.x;
    const int tid = threadIdx.x, w = tid >> 5, l = tid & 31;

    if (tid < KK) ssm[tid] = g_s[b * KK + tid];
    if (tid == 0) gss = 0.f;
    __syncthreads();

    const float4* P4 = (const float4*)(g_P + b * KK * DD);
    const float4* c4 = (const float4*)cent;
    float4* V4 = (float4*)V;

    float gloc = 0.f;
    #pragma unroll
    for (int kk = 0; kk < 4; kk++) {
        int k = w * 4 + kk;
        float4 pv = P4[k * 32 + l];
        float4 cv = c4[k * 32 + l];
        float sk = ssm[k];
        float4 v = make_float4(pv.x - sk * cv.x, pv.y - sk * cv.y,
                               pv.z - sk * cv.z, pv.w - sk * cv.w);
        float ss = v.x * v.x + v.y * v.y + v.z * v.z + v.w * v.w;
        #pragma unroll
        for (int o = 16; o > 0; o >>= 1)
            ss += __shfl_xor_sync(0xffffffffu, ss, o);
        float rinv = 1.f / fmaxf(sqrtf(ss), 1e-12f);
        v.x *= rinv; v.y *= rinv; v.z *= rinv; v.w *= rinv;
        V4[k * 32 + l] = v;
        gloc += v.x * v.x + v.y * v.y + v.z * v.z + v.w * v.w;
    }
    #pragma unroll
    for (int o = 16; o > 0; o >>= 1)
        gloc += __shfl_xor_sync(0xffffffffu, gloc, o);
    if (l == 0) atomicAdd(&gss, gloc);
    __syncthreads();

    float ginv = 1.f / fmaxf(sqrtf(gss), 1e-12f);
    float4* out4 = (float4*)(out + (size_t)b * KK * DD);
    #pragma unroll
    for (int kk = 0; kk < 4; kk++) {
        int k = w * 4 + kk;
        float4 v = V4[k * 32 + l];
        v.x *= ginv; v.y *= ginv; v.z *= ginv; v.w *= ginv;
        out4[k * 32 + l] = v;
    }
}

// ---------------------------------------------------------------------------
extern "C" void kernel_launch(void* const* d_in, const int* in_sizes, int n_in,
                              void* d_out, int out_size) {
    const float* x    = (const float*)d_in[0];
    const float* cent = (const float*)d_in[1];
    float* out        = (float*)d_out;

    const size_t smem = (size_t)(128 * 68 + 128 * 128 + 128 * 64 + 64) * sizeof(float);
    cudaFuncSetAttribute(nv_main, cudaFuncAttributeMaxDynamicSharedMemorySize, (int)smem);

    nv_zero<<<(BB * KK * DD + 511) / 512, 512>>>();
    nv_main<<<dim3(NN / TT, BB), 256, smem>>>(x, cent);
    nv_fin<<<BB, 512>>>(cent, out);
}